// round 3
// baseline (speedup 1.0000x reference)
#include <cuda_runtime.h>

#define NN     4096
#define NFEAT  1024
#define HALL   64      // 8 heads * 8 hid
#define NHEADS 8
#define NHID   8
#define NC     16
#define MAXDEG 512
#define SPLITS 4
#define KC     (NFEAT / SPLITS)   // 256
#define BM     128
#define BN     64
#define BK     16
#define ALPHA  0.2f

typedef unsigned long long ull;

// ---- scratch (device globals: no allocation allowed) ----
__device__ int   d_nbr[NN * MAXDEG];
__device__ int   d_deg[NN];
__device__ float d_Whp[SPLITS * NN * HALL];   // split-K partials
__device__ float d_Wh [NN * HALL];
__device__ float d_fsrc[NHEADS * NN];
__device__ float d_fdst[NHEADS * NN];
__device__ float d_h  [NN * HALL];            // layer-1 output (post-ELU)
__device__ float d_Wh2[NN * NC];
__device__ float d_f2s[NN];
__device__ float d_f2d[NN];

// ---- packed fp32x2 helpers (sm_103a) ----
__device__ __forceinline__ void fma2(ull& d, ull a, ull b) {
    asm("fma.rn.f32x2 %0, %1, %2, %0;" : "+l"(d) : "l"(a), "l"(b));
}
__device__ __forceinline__ ull pk(float x, float y) {
    ull r; asm("mov.b64 %0, {%1,%2};" : "=l"(r) : "f"(x), "f"(y)); return r;
}
__device__ __forceinline__ float2 upk(ull v) {
    float2 r; asm("mov.b64 {%0,%1}, %2;" : "=f"(r.x), "=f"(r.y) : "l"(v)); return r;
}

// ---- 1. build neighbor lists (deterministic ballot compaction, 1 HBM pass) ----
__global__ __launch_bounds__(256) void build_nbr(const float4* __restrict__ adj)
{
    int i = blockIdx.x;
    int tid = threadIdx.x, lane = tid & 31, w = tid >> 5;
    __shared__ int wc[8];
    const float4* row = adj + (size_t)i * (NN / 4);

    unsigned m[4]; int myc = 0;
#pragma unroll
    for (int r = 0; r < 4; r++) {
        int q = w * 128 + r * 32 + lane;
        float4 v = row[q];
        unsigned mm = (v.x > 0.f ? 1u : 0u) | (v.y > 0.f ? 2u : 0u)
                    | (v.z > 0.f ? 4u : 0u) | (v.w > 0.f ? 8u : 0u);
        m[r] = mm; myc += __popc(mm);
    }
    int tot = myc;
#pragma unroll
    for (int d = 16; d; d >>= 1) tot += __shfl_xor_sync(0xffffffffu, tot, d);
    if (lane == 0) wc[w] = tot;
    __syncthreads();
    int base = 0, deg = 0;
#pragma unroll
    for (int ww = 0; ww < 8; ww++) { int c = wc[ww]; deg += c; if (ww < w) base += c; }

    int* nb = d_nbr + (size_t)i * MAXDEG;
    int off = base;
#pragma unroll
    for (int r = 0; r < 4; r++) {
        int c = __popc(m[r]);
        int pre = c;
#pragma unroll
        for (int d = 1; d < 32; d <<= 1) {
            int t = __shfl_up_sync(0xffffffffu, pre, d);
            if (lane >= d) pre += t;
        }
        int rt = __shfl_sync(0xffffffffu, pre, 31);
        pre -= c;
        int p = off + pre;
        int jb = (w * 128 + r * 32 + lane) * 4;
        unsigned mm = m[r];
#pragma unroll
        for (int b = 0; b < 4; b++)
            if (mm & (1u << b)) { if (p < MAXDEG) nb[p] = jb + b; p++; }
        off += rt;
    }
    if (tid == 0) d_deg[i] = deg < MAXDEG ? deg : MAXDEG;
}

// ---- 2. SGEMM split-K with packed fma.rn.f32x2, B loaded straight from W_heads ----
__global__ __launch_bounds__(128) void gemm_wh(const float* __restrict__ x,
                                               const float* __restrict__ W_heads)
{
    __shared__ float As[BK][BM];   // transposed: As[k][m]
    __shared__ float Bs[BK][BN];
    int bm = blockIdx.x * BM;
    int k0 = blockIdx.y * KC;
    int tid = threadIdx.x;
    int tx = tid & 7, ty = tid >> 3;
    int m0 = ty * 8, n0 = tx * 8;

    ull acc[8][4];
#pragma unroll
    for (int r = 0; r < 8; r++)
#pragma unroll
        for (int c = 0; c < 4; c++) acc[r][c] = 0ull;

    for (int kc = 0; kc < KC; kc += BK) {
        // A tile 128x16: 512 float4, 4 per thread, transpose on store
#pragma unroll
        for (int r = 0; r < 4; r++) {
            int idx = tid + r * 128;
            int m = idx >> 2, q = idx & 3;
            float4 v = *(const float4*)(x + (size_t)(bm + m) * NFEAT + k0 + kc + q * 4);
            As[q * 4 + 0][m] = v.x;
            As[q * 4 + 1][m] = v.y;
            As[q * 4 + 2][m] = v.z;
            As[q * 4 + 3][m] = v.w;
        }
        // B tile 16x64 direct from W_heads[head][k][hid]: n4*4..+3 stay in one head
#pragma unroll
        for (int r = 0; r < 2; r++) {
            int idx = tid + r * 128;
            int kk = idx >> 4, n4 = idx & 15;
            const float* src = W_heads + (size_t)(n4 >> 1) * (NFEAT * NHID)
                             + (size_t)(k0 + kc + kk) * NHID + (n4 & 1) * 4;
            *(float4*)&Bs[kk][n4 * 4] = *(const float4*)src;
        }
        __syncthreads();
#pragma unroll
        for (int kk = 0; kk < BK; kk++) {
            float4 a0 = *(float4*)&As[kk][m0];
            float4 a1 = *(float4*)&As[kk][m0 + 4];
            float4 b0 = *(float4*)&Bs[kk][n0];
            float4 b1 = *(float4*)&Bs[kk][n0 + 4];
            ull bp0 = pk(b0.x, b0.y), bp1 = pk(b0.z, b0.w);
            ull bp2 = pk(b1.x, b1.y), bp3 = pk(b1.z, b1.w);
            float av[8] = {a0.x, a0.y, a0.z, a0.w, a1.x, a1.y, a1.z, a1.w};
#pragma unroll
            for (int r = 0; r < 8; r++) {
                ull ap = pk(av[r], av[r]);
                fma2(acc[r][0], ap, bp0);
                fma2(acc[r][1], ap, bp1);
                fma2(acc[r][2], ap, bp2);
                fma2(acc[r][3], ap, bp3);
            }
        }
        __syncthreads();
    }
    float* outp = d_Whp + (size_t)blockIdx.y * (NN * HALL);
#pragma unroll
    for (int r = 0; r < 8; r++) {
        float2 c0 = upk(acc[r][0]), c1 = upk(acc[r][1]);
        float2 c2 = upk(acc[r][2]), c3 = upk(acc[r][3]);
        float* dst = outp + (size_t)(bm + m0 + r) * HALL + n0;
        *(float4*)dst       = make_float4(c0.x, c0.y, c1.x, c1.y);
        *(float4*)(dst + 4) = make_float4(c2.x, c2.y, c3.x, c3.y);
    }
}

// ---- 3. fused: reduce split-K partials + attention logits (f_src/f_dst) ----
__global__ __launch_bounds__(256) void reduce_calc_f(const float* __restrict__ a_heads)
{
    __shared__ float sa[NHEADS * 2 * NHID];   // 128
    if (threadIdx.x < 128) sa[threadIdx.x] = a_heads[threadIdx.x];
    __syncthreads();
    int idx = blockIdx.x * 256 + threadIdx.x;   // over NN*NHEADS = 32768
    int i = idx >> 3, h = idx & 7;
    const float4* p = (const float4*)d_Whp;
    const int STR = NN * HALL / 4;
    float4 A = p[idx * 2],     B = p[idx * 2 + 1];
#pragma unroll
    for (int s = 1; s < SPLITS; s++) {
        float4 a = p[s * STR + idx * 2], b = p[s * STR + idx * 2 + 1];
        A.x += a.x; A.y += a.y; A.z += a.z; A.w += a.w;
        B.x += b.x; B.y += b.y; B.z += b.z; B.w += b.w;
    }
    ((float4*)d_Wh)[idx * 2]     = A;
    ((float4*)d_Wh)[idx * 2 + 1] = B;
    const float* a = sa + h * 16;
    float wv[8] = {A.x, A.y, A.z, A.w, B.x, B.y, B.z, B.w};
    float s = 0.f, d = 0.f;
#pragma unroll
    for (int k = 0; k < 8; k++) { s += wv[k] * a[k]; d += wv[k] * a[8 + k]; }
    d_fsrc[h * NN + i] = s;
    d_fdst[h * NN + i] = d;
}

// ---- 4. layer-1 sparse attention + ELU ----
__global__ __launch_bounds__(64) void attn1()
{
    int i = blockIdx.x;
    int t = threadIdx.x;        // t = h*8 + c
    int h = t >> 3;
    int deg = d_deg[i];
    float fs = d_fsrc[h * NN + i];
    const int* __restrict__ nb = d_nbr + (size_t)i * MAXDEG;
    float s = 0.0f, acc = 0.0f;
#pragma unroll 4
    for (int q = 0; q < deg; q++) {
        int j = nb[q];
        float e = fs + d_fdst[h * NN + j];
        e = e > 0.0f ? e : ALPHA * e;
        float p = __expf(e);             // shift-free softmax (|e| small)
        s += p;
        acc += p * d_Wh[(size_t)j * HALL + t];
    }
    float v = acc / s;
    d_h[(size_t)i * HALL + t] = v > 0.0f ? v : expm1f(v);   // ELU
}

// ---- 5. fused: Wh2 = h @ W_final + layer-2 logits ----
__global__ __launch_bounds__(256) void gemm2_f2(const float* __restrict__ Wf,
                                                const float* __restrict__ a_final)
{
    __shared__ float sw[HALL * NC];   // 1024
    __shared__ float sa2[2 * NC];
    ((float4*)sw)[threadIdx.x] = ((const float4*)Wf)[threadIdx.x];
    if (threadIdx.x < 32) sa2[threadIdx.x] = a_final[threadIdx.x];
    __syncthreads();
    int i = blockIdx.x * 256 + threadIdx.x;
    float hreg[HALL];
    const float4* hp = (const float4*)(d_h + (size_t)i * HALL);
#pragma unroll
    for (int q = 0; q < 16; q++) {
        float4 v = hp[q];
        hreg[q * 4] = v.x; hreg[q * 4 + 1] = v.y; hreg[q * 4 + 2] = v.z; hreg[q * 4 + 3] = v.w;
    }
    float o[NC];
#pragma unroll
    for (int c = 0; c < NC; c++) o[c] = 0.f;
#pragma unroll
    for (int k = 0; k < HALL; k++) {
        float hv = hreg[k];
        const float4* wr = (const float4*)(sw + k * NC);
#pragma unroll
        for (int q = 0; q < 4; q++) {
            float4 wv = wr[q];
            o[q * 4]     += hv * wv.x;
            o[q * 4 + 1] += hv * wv.y;
            o[q * 4 + 2] += hv * wv.z;
            o[q * 4 + 3] += hv * wv.w;
        }
    }
    float s = 0.f, d = 0.f;
#pragma unroll
    for (int c = 0; c < NC; c++) { s += o[c] * sa2[c]; d += o[c] * sa2[NC + c]; }
    float4* op = (float4*)(d_Wh2 + (size_t)i * NC);
    op[0] = make_float4(o[0], o[1], o[2], o[3]);
    op[1] = make_float4(o[4], o[5], o[6], o[7]);
    op[2] = make_float4(o[8], o[9], o[10], o[11]);
    op[3] = make_float4(o[12], o[13], o[14], o[15]);
    d_f2s[i] = s;
    d_f2d[i] = d;
}

// ---- 6. layer-2 sparse attention + log_softmax (one warp per row) ----
__global__ __launch_bounds__(128) void attn2(float* __restrict__ out)
{
    int i = blockIdx.x * 4 + (threadIdx.x >> 5);
    int lane = threadIdx.x & 31;
    int c = lane & 15, half = lane >> 4;
    int deg = d_deg[i];
    float fs = d_f2s[i];
    const int* __restrict__ nb = d_nbr + (size_t)i * MAXDEG;
    float s = 0.0f, acc = 0.0f;
#pragma unroll 4
    for (int q = half; q < deg; q += 2) {
        int j = nb[q];
        float e = fs + d_f2d[j];
        e = e > 0.0f ? e : ALPHA * e;
        float p = __expf(e);
        s += p;
        acc += p * d_Wh2[(size_t)j * NC + c];
    }
    acc += __shfl_xor_sync(0xffffffffu, acc, 16);
    s   += __shfl_xor_sync(0xffffffffu, s, 16);
    float o = acc / s;
    float m = o;
#pragma unroll
    for (int d = 8; d; d >>= 1) m = fmaxf(m, __shfl_xor_sync(0xffffffffu, m, d));
    float ex = __expf(o - m);
    float se = ex;
#pragma unroll
    for (int d = 8; d; d >>= 1) se += __shfl_xor_sync(0xffffffffu, se, d);
    if (half == 0) out[(size_t)i * NC + c] = o - m - logf(se);
}

extern "C" void kernel_launch(void* const* d_in, const int* in_sizes, int n_in,
                              void* d_out, int out_size)
{
    const float* x       = (const float*)d_in[0];
    const float* adj     = (const float*)d_in[1];
    const float* W_heads = (const float*)d_in[2];
    const float* a_heads = (const float*)d_in[3];
    const float* W_final = (const float*)d_in[4];
    const float* a_final = (const float*)d_in[5];
    float* out = (float*)d_out;

    static cudaStream_t s2 = nullptr;
    static cudaEvent_t evF = nullptr, evJ = nullptr;
    if (!s2) {
        cudaStreamCreateWithFlags(&s2, cudaStreamNonBlocking);
        cudaEventCreateWithFlags(&evF, cudaEventDisableTiming);
        cudaEventCreateWithFlags(&evJ, cudaEventDisableTiming);
    }

    // fork: adj scan (HBM-bound) overlaps GEMM chain (FMA-bound)
    cudaEventRecord(evF, 0);
    cudaStreamWaitEvent(s2, evF, 0);
    build_nbr<<<NN, 256, 0, s2>>>((const float4*)adj);
    cudaEventRecord(evJ, s2);

    gemm_wh<<<dim3(NN / BM, SPLITS), 128>>>(x, W_heads);
    reduce_calc_f<<<NN * NHEADS / 256, 256>>>(a_heads);

    // join before attention needs neighbor lists
    cudaStreamWaitEvent(0, evJ, 0);
    attn1<<<NN, 64>>>();
    gemm2_f2<<<NN / 256, 256>>>(W_final, a_final);
    attn2<<<NN / 4, 128>>>(out);
}